// round 10
// baseline (speedup 1.0000x reference)
#include <cuda_runtime.h>
#include <cuda_bf16.h>
#include <math.h>
#include <stdint.h>

#define B_      2
#define L_      1024
#define DM      768
#define DI      1536
#define DS      16
#define DTR     48
#define VOCAB_  50264
#define ROWS    (B_*L_)   // 2048

// ---------------- scratch (static device memory; no allocation) ----------------
__device__ float g_x[ROWS*DM];
__device__ float g_xr[ROWS*2*DI];
__device__ float g_u[ROWS*DI];
__device__ float g_xdbl[ROWS*80];
__device__ float g_delta[ROWS*DI];
// split activation buffers (max 2048x1536)
__device__ __nv_bfloat16 g_ahi[ROWS*DI];
__device__ __nv_bfloat16 g_alo[ROWS*DI];
// split weight buffers (max = embedding 50264x768)
__device__ __nv_bfloat16 g_whi[(size_t)VOCAB_*DM];
__device__ __nv_bfloat16 g_wlo[(size_t)VOCAB_*DM];

// ================= helpers =================
__device__ __forceinline__ uint32_t smem_u32(const void* p) {
    uint32_t a;
    asm("{ .reg .u64 t; cvta.to.shared.u64 t, %1; cvt.u32.u64 %0, t; }" : "=r"(a) : "l"(p));
    return a;
}
__device__ __forceinline__ void ldsm4(uint32_t* r, uint32_t addr) {
    asm volatile("ldmatrix.sync.aligned.m8n8.x4.shared.b16 {%0,%1,%2,%3}, [%4];"
        : "=r"(r[0]), "=r"(r[1]), "=r"(r[2]), "=r"(r[3]) : "r"(addr));
}
__device__ __forceinline__ void mma_bf16(float* c, const uint32_t* a, const uint32_t* b) {
    asm volatile("mma.sync.aligned.m16n8k16.row.col.f32.bf16.bf16.f32 "
        "{%0,%1,%2,%3},{%4,%5,%6,%7},{%8,%9},{%0,%1,%2,%3};"
        : "+f"(c[0]), "+f"(c[1]), "+f"(c[2]), "+f"(c[3])
        : "r"(a[0]), "r"(a[1]), "r"(a[2]), "r"(a[3]), "r"(b[0]), "r"(b[1]));
}
__device__ __forceinline__ void cp16(uint32_t dst, const void* src, bool valid) {
    int sz = valid ? 16 : 0;
    asm volatile("cp.async.cg.shared.global [%0], [%1], 16, %2;"
                 :: "r"(dst), "l"(src), "r"(sz) : "memory");
}
__device__ __forceinline__ void cp_commit() {
    asm volatile("cp.async.commit_group;" ::: "memory");
}
__device__ __forceinline__ void bf16_split(float v, __nv_bfloat16& h, __nv_bfloat16& l) {
    h = __float2bfloat16(v);
    l = __float2bfloat16(v - __bfloat162float(h));
}

// ================= split fp32 -> bf16 hi + bf16 lo (weights) =================
__global__ void split_kernel(const float* __restrict__ in,
                             __nv_bfloat16* __restrict__ hi,
                             __nv_bfloat16* __restrict__ lo,
                             int n4)
{
    int i = blockIdx.x*blockDim.x + threadIdx.x;
    if (i >= n4) return;
    float4 v = ((const float4*)in)[i];
    __nv_bfloat16 h0,h1,h2,h3,l0,l1,l2,l3;
    bf16_split(v.x, h0, l0); bf16_split(v.y, h1, l1);
    bf16_split(v.z, h2, l2); bf16_split(v.w, h3, l3);
    ushort4 ho, lq;
    ho.x = __bfloat16_as_ushort(h0); ho.y = __bfloat16_as_ushort(h1);
    ho.z = __bfloat16_as_ushort(h2); ho.w = __bfloat16_as_ushort(h3);
    lq.x = __bfloat16_as_ushort(l0); lq.y = __bfloat16_as_ushort(l1);
    lq.z = __bfloat16_as_ushort(l2); lq.w = __bfloat16_as_ushort(l3);
    ((ushort4*)hi)[i] = ho;
    ((ushort4*)lo)[i] = lq;
}

// ================= bf16 split-precision tensor GEMM =================
// C[M,N] = A[M,K] @ W[N,K]^T.  acc += hi*hi + lo*hi + hi*lo.
// Block tile 128x128, k-chunk 32, 8 warps (4M x 2N), warp tile 32x64.
// Stage row format (128B): bytes [0,64) = hi k32, [64,128) = lo k32.
// 3-stage cp.async, 2 CTAs/SM.  Grid: x = M-tiles (fast), y = N-tiles.
// ep: 0 = none, 2 = acc + resid[m*N+n]
#define SB_OFF 16384
#define STG    32768
#define SM_BYTES (3*STG)   // 98304

__global__ void __launch_bounds__(256, 2) gemm_bf16(
    const __nv_bfloat16* __restrict__ Ahi, const __nv_bfloat16* __restrict__ Alo, int K,
    const __nv_bfloat16* __restrict__ Bhi, const __nv_bfloat16* __restrict__ Blo, int N,
    float* __restrict__ C, int ep, const float* __restrict__ resid)
{
    extern __shared__ char sm[];
    const uint32_t sb = smem_u32(sm);
    const int tid = threadIdx.x, wid = tid >> 5, lane = tid & 31;
    const int wm = wid & 3, wn = wid >> 2;
    const int m0 = blockIdx.x * 128;
    const int n0 = blockIdx.y * 128;

    float acc[2][8][4];
    #pragma unroll
    for (int i = 0; i < 2; i++)
        #pragma unroll
        for (int j = 0; j < 8; j++)
            #pragma unroll
            for (int v = 0; v < 4; v++) acc[i][j][v] = 0.f;

    // gmem->smem: thread t handles (row = t>>1, half = t&1): 4 x 16B for A, 4 for B
    const int lrow = tid >> 1;
    const int lhalf = tid & 1;

    // ldmatrix address components
    const int arow = wm*32 + (lane & 15);
    const int acbit = lane >> 4;
    const int brow0 = wn*64 + (lane & 7) + ((lane >> 4) << 3);
    const int bcbit = (lane >> 3) & 1;

    const int nk = K >> 5;

    const __nv_bfloat16* Asrc = (lhalf ? Alo : Ahi) + (size_t)(m0 + lrow)*K;
    const bool bvalid = (n0 + lrow) < N;
    const __nv_bfloat16* Bsrc = (lhalf ? Blo : Bhi) + (size_t)(bvalid ? (n0 + lrow) : 0)*K;

    auto issue = [&](int kc) {
        const uint32_t base = sb + (kc % 3)*STG;
        const int k0 = kc << 5;
        #pragma unroll
        for (int c = 0; c < 4; c++) {
            uint32_t off = (uint32_t)(lrow*128 + (((lhalf*4 + c) ^ (lrow & 7)) << 4));
            cp16(base + off, Asrc + k0 + c*8, true);
            cp16(base + SB_OFF + off, Bsrc + k0 + c*8, bvalid);
        }
        cp_commit();
    };

    issue(0);
    if (nk > 1) issue(1);
    for (int kc = 0; kc < nk; kc++) {
        if (kc == nk - 1)
            asm volatile("cp.async.wait_group 0;" ::: "memory");
        else
            asm volatile("cp.async.wait_group 1;" ::: "memory");
        __syncthreads();
        if (kc + 2 < nk) issue(kc + 2);

        const uint32_t stg = sb + (kc % 3)*STG;
        #pragma unroll
        for (int ks = 0; ks < 2; ks++) {
            uint32_t ahi[2][4], alo[2][4];
            #pragma unroll
            for (int mi = 0; mi < 2; mi++) {
                int row = arow + mi*16;
                int ch = ks*2 + acbit;
                uint32_t ohi = (uint32_t)(row*128 + ((ch ^ (row & 7)) << 4));
                uint32_t olo = (uint32_t)(row*128 + (((ch + 4) ^ (row & 7)) << 4));
                ldsm4(ahi[mi], stg + ohi);
                ldsm4(alo[mi], stg + olo);
            }
            #pragma unroll
            for (int h = 0; h < 2; h++) {
                uint32_t bhi[2][4], blo[2][4];
                #pragma unroll
                for (int p = 0; p < 2; p++) {
                    int row = brow0 + h*32 + p*16;
                    int ch = ks*2 + bcbit;
                    uint32_t ohi = (uint32_t)(row*128 + ((ch ^ (row & 7)) << 4));
                    uint32_t olo = (uint32_t)(row*128 + (((ch + 4) ^ (row & 7)) << 4));
                    ldsm4(bhi[p], stg + SB_OFF + ohi);
                    ldsm4(blo[p], stg + SB_OFF + olo);
                }
                #pragma unroll
                for (int mi = 0; mi < 2; mi++)
                    #pragma unroll
                    for (int p = 0; p < 2; p++)
                        #pragma unroll
                        for (int q = 0; q < 2; q++) {
                            float* a = acc[mi][h*4 + p*2 + q];
                            mma_bf16(a, ahi[mi], &bhi[p][2*q]);
                            mma_bf16(a, alo[mi], &bhi[p][2*q]);
                            mma_bf16(a, ahi[mi], &blo[p][2*q]);
                        }
            }
        }
    }

    // epilogue
    const int gid = lane >> 2, tig = lane & 3;
    #pragma unroll
    for (int mi = 0; mi < 2; mi++) {
        #pragma unroll
        for (int j = 0; j < 8; j++) {
            int m = m0 + wm*32 + mi*16 + gid;
            int n = n0 + wn*64 + j*8 + tig*2;
            if (n < N) {
                float2 v0 = make_float2(acc[mi][j][0], acc[mi][j][1]);
                float2 v1 = make_float2(acc[mi][j][2], acc[mi][j][3]);
                if (ep == 2) {
                    const float2 r0 = *(const float2*)(resid + (size_t)m*N + n);
                    const float2 r1 = *(const float2*)(resid + (size_t)(m+8)*N + n);
                    v0.x += r0.x; v0.y += r0.y;
                    v1.x += r1.x; v1.y += r1.y;
                }
                *(float2*)(C + (size_t)m*N + n) = v0;
                *(float2*)(C + (size_t)(m+8)*N + n) = v1;
            }
        }
    }
}

// ================= other kernels =================
__global__ void embed_kernel(const int* __restrict__ ids,
                             const float* __restrict__ emb,
                             float* __restrict__ x)
{
    int idx = blockIdx.x*blockDim.x + threadIdx.x;
    if (idx >= ROWS*DM) return;
    int row = idx / DM, c = idx % DM;
    x[idx] = emb[(size_t)ids[row]*DM + c];
}

// rmsnorm + emit bf16 hi/lo split directly
__global__ void rmsnorm_split_kernel(const float* __restrict__ x,
                                     const float* __restrict__ w,
                                     __nv_bfloat16* __restrict__ ohi,
                                     __nv_bfloat16* __restrict__ olo)
{
    __shared__ float red[8];
    int row = blockIdx.x;
    const float* xr = x + (size_t)row*DM;
    float s = 0.f;
    for (int c = threadIdx.x; c < DM; c += 256) { float v = xr[c]; s += v*v; }
    #pragma unroll
    for (int o = 16; o; o >>= 1) s += __shfl_xor_sync(0xffffffffu, s, o);
    if ((threadIdx.x & 31) == 0) red[threadIdx.x >> 5] = s;
    __syncthreads();
    if (threadIdx.x < 8) {
        s = red[threadIdx.x];
        #pragma unroll
        for (int o = 4; o; o >>= 1) s += __shfl_xor_sync(0xffu, s, o);
        if (threadIdx.x == 0) red[0] = s;
    }
    __syncthreads();
    float scale = rsqrtf(red[0] / (float)DM + 1e-5f);
    for (int c = threadIdx.x; c < DM; c += 256) {
        float v = xr[c] * scale * w[c];
        __nv_bfloat16 h, l;
        bf16_split(v, h, l);
        ohi[(size_t)row*DM + c] = h;
        olo[(size_t)row*DM + c] = l;
    }
}

// small FFMA GEMM (dt_proj).  ep: 0=none, 1=softplus(acc+bias[n])
__global__ void __launch_bounds__(256, 2) gemm_nt(
    const float* __restrict__ A, int lda,
    const float* __restrict__ W,
    float* __restrict__ C,
    int N, int K, int ep,
    const float* __restrict__ bias)
{
    __shared__ float As[8][128];
    __shared__ float Bs[8][128];
    const int tid = threadIdx.x;
    const int tx = tid & 15;
    const int ty = tid >> 4;
    const int m0 = blockIdx.y * 128;
    const int n0 = blockIdx.x * 128;
    const int lr = tid >> 1;
    const int lc = (tid & 1) * 4;

    float acc[8][8];
    #pragma unroll
    for (int i = 0; i < 8; i++)
        #pragma unroll
        for (int j = 0; j < 8; j++) acc[i][j] = 0.f;

    const float* Aptr = A + (size_t)(m0 + lr)*lda + lc;
    const bool wvalid = (n0 + lr) < N;
    const float* Wptr = W + (size_t)(wvalid ? (n0 + lr) : 0)*K + lc;

    for (int k0 = 0; k0 < K; k0 += 8) {
        float4 av = *(const float4*)(Aptr + k0);
        float4 bv = make_float4(0.f, 0.f, 0.f, 0.f);
        if (wvalid) bv = *(const float4*)(Wptr + k0);
        __syncthreads();
        As[lc+0][lr] = av.x; As[lc+1][lr] = av.y; As[lc+2][lr] = av.z; As[lc+3][lr] = av.w;
        Bs[lc+0][lr] = bv.x; Bs[lc+1][lr] = bv.y; Bs[lc+2][lr] = bv.z; Bs[lc+3][lr] = bv.w;
        __syncthreads();
        #pragma unroll
        for (int k = 0; k < 8; k++) {
            float4 a0 = *(const float4*)&As[k][ty*8];
            float4 a1 = *(const float4*)&As[k][ty*8+4];
            float4 b0 = *(const float4*)&Bs[k][tx*8];
            float4 b1 = *(const float4*)&Bs[k][tx*8+4];
            float ar[8] = {a0.x,a0.y,a0.z,a0.w,a1.x,a1.y,a1.z,a1.w};
            float br[8] = {b0.x,b0.y,b0.z,b0.w,b1.x,b1.y,b1.z,b1.w};
            #pragma unroll
            for (int i = 0; i < 8; i++)
                #pragma unroll
                for (int j = 0; j < 8; j++)
                    acc[i][j] = fmaf(ar[i], br[j], acc[i][j]);
        }
    }

    #pragma unroll
    for (int i = 0; i < 8; i++) {
        int m = m0 + ty*8 + i;
        #pragma unroll
        for (int j = 0; j < 8; j++) {
            int n = n0 + tx*8 + j;
            if (n < N) {
                float v = acc[i][j];
                if (ep == 1) {
                    v += bias[n];
                    v = (v > 20.f) ? v : log1pf(expf(v));
                }
                C[(size_t)m*N + n] = v;
            }
        }
    }
}

// depthwise causal conv + bias + silu -> u (fp32) AND u hi/lo (bf16 split)
__global__ void conv_silu_kernel(const float* __restrict__ xr,
                                 const float* __restrict__ cw,
                                 const float* __restrict__ cb,
                                 float* __restrict__ u,
                                 __nv_bfloat16* __restrict__ uhi,
                                 __nv_bfloat16* __restrict__ ulo)
{
    int idx = blockIdx.x*blockDim.x + threadIdx.x;
    if (idx >= ROWS*DI) return;
    int d = idx % DI;
    int row = idx / DI;
    int t = row % L_;
    float acc = cb[d];
    #pragma unroll
    for (int j = 0; j < 4; ++j) {
        int tt = t - 3 + j;
        if (tt >= 0)
            acc = fmaf(cw[d*4 + j], xr[(size_t)(row - 3 + j)*(2*DI) + d], acc);
    }
    float v = acc / (1.f + __expf(-acc));
    u[idx] = v;
    __nv_bfloat16 h, l;
    bf16_split(v, h, l);
    uhi[idx] = h;
    ulo[idx] = l;
}

// selective scan + fused gate + bf16 split output
__global__ void scan_kernel(const float* __restrict__ delta,
                            const float* __restrict__ u,
                            const float* __restrict__ xdbl,
                            const float* __restrict__ alog,
                            const float* __restrict__ Dv,
                            const float* __restrict__ xr,
                            __nv_bfloat16* __restrict__ yhi,
                            __nv_bfloat16* __restrict__ ylo)
{
    int gid = blockIdx.x*blockDim.x + threadIdx.x;
    int ch = gid >> 4;
    if (ch >= B_*DI) return;
    int n = gid & 15;
    int b = ch / DI, d = ch % DI;
    float An = -__expf(alog[d*DS + n]);
    float Dd = Dv[d];
    float state = 0.f;
    const float* drow = delta + (size_t)b*L_*DI + d;
    const float* urow = u     + (size_t)b*L_*DI + d;
    const float* xrow = xdbl  + (size_t)b*L_*80 + DTR + n;
    const float* rrow = xr    + (size_t)b*L_*(2*DI) + DI + d;
    __nv_bfloat16* yh = yhi + (size_t)b*L_*DI + d;
    __nv_bfloat16* yl = ylo + (size_t)b*L_*DI + d;
    for (int t = 0; t < L_; ++t) {
        float dt = drow[(size_t)t*DI];
        float uu = urow[(size_t)t*DI];
        float Bn = xrow[(size_t)t*80];
        float Cn = xrow[(size_t)t*80 + DS];
        float dA = __expf(dt * An);
        state = fmaf(dA, state, dt * Bn * uu);
        float p = state * Cn;
        p += __shfl_xor_sync(0xffffffffu, p, 8);
        p += __shfl_xor_sync(0xffffffffu, p, 4);
        p += __shfl_xor_sync(0xffffffffu, p, 2);
        p += __shfl_xor_sync(0xffffffffu, p, 1);
        if (n == 0) {
            float r = rrow[(size_t)t*(2*DI)];
            float g = r / (1.f + __expf(-r));
            float yv = (p + uu * Dd) * g;
            __nv_bfloat16 h, l;
            bf16_split(yv, h, l);
            yh[(size_t)t*DI] = h;
            yl[(size_t)t*DI] = l;
        }
    }
}

// ================= launcher =================
static inline void do_split(const float* src, __nv_bfloat16* hi, __nv_bfloat16* lo, size_t n)
{
    int n4 = (int)(n >> 2);
    split_kernel<<<(n4 + 255)/256, 256>>>(src, hi, lo, n4);
}

extern "C" void kernel_launch(void* const* d_in, const int* in_sizes, int n_in,
                              void* d_out, int out_size)
{
    (void)in_sizes; (void)n_in; (void)out_size;
    const int*   ids  = (const int*)d_in[0];
    const float* emb  = (const float*)d_in[2];
    const float* inw  = (const float*)d_in[3];
    const float* cw   = (const float*)d_in[4];
    const float* cb   = (const float*)d_in[5];
    const float* xpw  = (const float*)d_in[6];
    const float* dtw  = (const float*)d_in[7];
    const float* dtb  = (const float*)d_in[8];
    const float* alog = (const float*)d_in[9];
    const float* Dv   = (const float*)d_in[10];
    const float* outw = (const float*)d_in[11];
    const float* nw   = (const float*)d_in[12];
    const float* nfw  = (const float*)d_in[13];
    float* out = (float*)d_out;

    float *x, *xr, *u, *xdbl, *delta;
    __nv_bfloat16 *ahi, *alo, *whi, *wlo;
    cudaGetSymbolAddress((void**)&x,     g_x);
    cudaGetSymbolAddress((void**)&xr,    g_xr);
    cudaGetSymbolAddress((void**)&u,     g_u);
    cudaGetSymbolAddress((void**)&xdbl,  g_xdbl);
    cudaGetSymbolAddress((void**)&delta, g_delta);
    cudaGetSymbolAddress((void**)&ahi,   g_ahi);
    cudaGetSymbolAddress((void**)&alo,   g_alo);
    cudaGetSymbolAddress((void**)&whi,   g_whi);
    cudaGetSymbolAddress((void**)&wlo,   g_wlo);

    static bool attr_done = false;
    if (!attr_done) {
        cudaFuncSetAttribute(gemm_bf16, cudaFuncAttributeMaxDynamicSharedMemorySize, SM_BYTES);
        attr_done = true;
    }

    embed_kernel<<<(ROWS*DM + 255)/256, 256>>>(ids, emb, x);

    for (int l = 0; l < 2; ++l) {
        // rmsnorm -> xn split (direct)
        rmsnorm_split_kernel<<<ROWS, 256>>>(x, nw + l*DM, ahi, alo);
        // in_proj: [2048,768] @ [3072,768]^T -> xr [2048,3072]
        do_split(inw + (size_t)l*2*DI*DM, whi, wlo, (size_t)2*DI*DM);
        gemm_bf16<<<dim3(ROWS/128, (2*DI + 127)/128), 256, SM_BYTES>>>(
            ahi, alo, DM, whi, wlo, 2*DI, xr, 0, nullptr);
        // conv + silu -> u fp32 + u split (overwrites ahi/alo)
        conv_silu_kernel<<<(ROWS*DI + 255)/256, 256>>>(
            xr, cw + l*DI*4, cb + l*DI, u, ahi, alo);
        // x_dbl = u @ x_proj^T : [2048, 80]
        do_split(xpw + (size_t)l*80*DI, whi, wlo, (size_t)80*DI);
        gemm_bf16<<<dim3(ROWS/128, 1), 256, SM_BYTES>>>(
            ahi, alo, DI, whi, wlo, 80, xdbl, 0, nullptr);
        // delta = softplus(x_dbl[:, :48] @ dt_proj^T + dt_b)
        gemm_nt<<<dim3(DI/128, ROWS/128), 256>>>(
            xdbl, 80, dtw + (size_t)l*DI*DTR, delta, DI, DTR, 1, dtb + l*DI);
        // scan + gate -> y split (overwrites ahi/alo; u fp32 still intact)
        scan_kernel<<<(B_*DI*16)/256, 256>>>(
            delta, u, xdbl, alog + l*DI*DS, Dv + l*DI, xr, ahi, alo);
        // out_proj: [2048,1536] @ [768,1536]^T + x -> x
        do_split(outw + (size_t)l*DM*DI, whi, wlo, (size_t)DM*DI);
        gemm_bf16<<<dim3(ROWS/128, (DM + 127)/128), 256, SM_BYTES>>>(
            ahi, alo, DI, whi, wlo, DM, x, 2, x);
    }

    // final rmsnorm -> xn split
    rmsnorm_split_kernel<<<ROWS, 256>>>(x, nfw, ahi, alo);
    // logits: [2048,768] @ [50264,768]^T -> out [2048,50264]
    do_split(emb, whi, wlo, (size_t)VOCAB_*DM);
    gemm_bf16<<<dim3(ROWS/128, (VOCAB_ + 127)/128), 256, SM_BYTES>>>(
        ahi, alo, DM, whi, wlo, VOCAB_, out, 0, nullptr);
}

// round 14
// speedup vs baseline: 1.3504x; 1.3504x over previous
#include <cuda_runtime.h>
#include <cuda_bf16.h>
#include <math.h>
#include <stdint.h>

#define B_      2
#define L_      1024
#define DM      768
#define DI      1536
#define DS      16
#define DTR     48
#define VOCAB_  50264
#define ROWS    (B_*L_)   // 2048

// ---------------- scratch (static device memory; no allocation) ----------------
__device__ float g_x[ROWS*DM];
__device__ float g_xr[ROWS*2*DI];
__device__ float g_u[ROWS*DI];
__device__ float g_xdbl[ROWS*80];
__device__ float g_delta[ROWS*DI];
// split activation buffers (max 2048x1536)
__device__ __nv_bfloat16 g_ahi[ROWS*DI];
__device__ __nv_bfloat16 g_alo[ROWS*DI];
// split weight buffers (max = embedding 50264x768)
__device__ __nv_bfloat16 g_whi[(size_t)VOCAB_*DM];
__device__ __nv_bfloat16 g_wlo[(size_t)VOCAB_*DM];

// ================= helpers =================
__device__ __forceinline__ uint32_t smem_u32(const void* p) {
    uint32_t a;
    asm("{ .reg .u64 t; cvta.to.shared.u64 t, %1; cvt.u32.u64 %0, t; }" : "=r"(a) : "l"(p));
    return a;
}
__device__ __forceinline__ void ldsm4(uint32_t* r, uint32_t addr) {
    asm volatile("ldmatrix.sync.aligned.m8n8.x4.shared.b16 {%0,%1,%2,%3}, [%4];"
        : "=r"(r[0]), "=r"(r[1]), "=r"(r[2]), "=r"(r[3]) : "r"(addr));
}
__device__ __forceinline__ void mma_bf16(float* c, const uint32_t* a, const uint32_t* b) {
    asm volatile("mma.sync.aligned.m16n8k16.row.col.f32.bf16.bf16.f32 "
        "{%0,%1,%2,%3},{%4,%5,%6,%7},{%8,%9},{%0,%1,%2,%3};"
        : "+f"(c[0]), "+f"(c[1]), "+f"(c[2]), "+f"(c[3])
        : "r"(a[0]), "r"(a[1]), "r"(a[2]), "r"(a[3]), "r"(b[0]), "r"(b[1]));
}
__device__ __forceinline__ void cp16(uint32_t dst, const void* src, bool valid) {
    int sz = valid ? 16 : 0;
    asm volatile("cp.async.cg.shared.global [%0], [%1], 16, %2;"
                 :: "r"(dst), "l"(src), "r"(sz) : "memory");
}
__device__ __forceinline__ void cp_commit() {
    asm volatile("cp.async.commit_group;" ::: "memory");
}
__device__ __forceinline__ void bf16_split(float v, __nv_bfloat16& h, __nv_bfloat16& l) {
    h = __float2bfloat16(v);
    l = __float2bfloat16(v - __bfloat162float(h));
}

// ================= split fp32 -> bf16 hi + bf16 lo (weights) =================
__global__ void split_kernel(const float* __restrict__ in,
                             __nv_bfloat16* __restrict__ hi,
                             __nv_bfloat16* __restrict__ lo,
                             int n4)
{
    int i = blockIdx.x*blockDim.x + threadIdx.x;
    if (i >= n4) return;
    float4 v = ((const float4*)in)[i];
    __nv_bfloat16 h0,h1,h2,h3,l0,l1,l2,l3;
    bf16_split(v.x, h0, l0); bf16_split(v.y, h1, l1);
    bf16_split(v.z, h2, l2); bf16_split(v.w, h3, l3);
    ushort4 ho, lq;
    ho.x = __bfloat16_as_ushort(h0); ho.y = __bfloat16_as_ushort(h1);
    ho.z = __bfloat16_as_ushort(h2); ho.w = __bfloat16_as_ushort(h3);
    lq.x = __bfloat16_as_ushort(l0); lq.y = __bfloat16_as_ushort(l1);
    lq.z = __bfloat16_as_ushort(l2); lq.w = __bfloat16_as_ushort(l3);
    ((ushort4*)hi)[i] = ho;
    ((ushort4*)lo)[i] = lq;
}

// ================= bf16 split-precision tensor GEMM =================
// C[M,N] = A[M,K] @ W[N,K]^T, A/W pre-split bf16 hi/lo.
// acc += hi*hi + lo*hi + hi*lo (fp32 accum in mma).
// Block tile 128x128, k-chunk 64, 8 warps (4M x 2N), warp tile 32x64.
// 3-stage cp.async (192KB smem), 1 CTA/SM.  Grid: x = M-tiles, y = N-tiles.
// ep: 0 = none, 2 = acc + resid[m*N+n]
#define SA_HI 0
#define SA_LO 16384
#define SB_HI 32768
#define SB_LO 49152
#define STG   65536
#define SM_BYTES (3*STG)   // 196608

__global__ void __launch_bounds__(256, 1) gemm_bf16(
    const __nv_bfloat16* __restrict__ Ahi, const __nv_bfloat16* __restrict__ Alo, int K,
    const __nv_bfloat16* __restrict__ Bhi, const __nv_bfloat16* __restrict__ Blo, int N,
    float* __restrict__ C, int ep, const float* __restrict__ resid)
{
    extern __shared__ char sm[];
    const uint32_t sb = smem_u32(sm);
    const int tid = threadIdx.x, wid = tid >> 5, lane = tid & 31;
    const int wm = wid & 3, wn = wid >> 2;
    const int m0 = blockIdx.x * 128;
    const int n0 = blockIdx.y * 128;

    float acc[2][8][4];
    #pragma unroll
    for (int i = 0; i < 2; i++)
        #pragma unroll
        for (int j = 0; j < 8; j++)
            #pragma unroll
            for (int v = 0; v < 4; v++) acc[i][j][v] = 0.f;

    // gmem->smem load indices (each thread: 4 rows x 16B per buffer)
    const int lrow = tid >> 3;          // 0..31 base row
    const int lchk = tid & 7;           // 16B chunk within 128B row

    // ldmatrix address components
    const int arow = wm*32 + (lane & 15);
    const int acbit = lane >> 4;
    const int brow0 = wn*64 + (lane & 7) + ((lane >> 4) << 3);
    const int bcbit = (lane >> 3) & 1;

    const int nk = K >> 6;

    auto issue = [&](int kc) {
        const int s = kc % 3;
        const int k0 = kc << 6;
        const uint32_t base = sb + s*STG;
        #pragma unroll
        for (int i = 0; i < 4; i++) {
            int r = lrow + i*32;
            size_t ga = (size_t)(m0 + r)*K + k0 + lchk*8;
            uint32_t off = (uint32_t)(r*128 + ((lchk ^ (r & 7)) << 4));
            cp16(base + SA_HI + off, Ahi + ga, true);
            cp16(base + SA_LO + off, Alo + ga, true);
            int n = n0 + r;
            bool v = n < N;
            size_t gb = (size_t)(v ? n : 0)*K + k0 + lchk*8;
            cp16(base + SB_HI + off, Bhi + gb, v);
            cp16(base + SB_LO + off, Blo + gb, v);
        }
        cp_commit();
    };

    issue(0);
    if (nk > 1) issue(1);
    for (int kc = 0; kc < nk; kc++) {
        if (kc == nk - 1)
            asm volatile("cp.async.wait_group 0;" ::: "memory");
        else
            asm volatile("cp.async.wait_group 1;" ::: "memory");
        __syncthreads();
        if (kc + 2 < nk) issue(kc + 2);

        const uint32_t stg = sb + (kc % 3)*STG;
        #pragma unroll
        for (int ks = 0; ks < 4; ks++) {
            uint32_t ahi[2][4], alo[2][4];
            #pragma unroll
            for (int mi = 0; mi < 2; mi++) {
                int row = arow + mi*16;
                int chunk = ks*2 + acbit;
                uint32_t off = (uint32_t)(row*128 + ((chunk ^ (row & 7)) << 4));
                ldsm4(ahi[mi], stg + SA_HI + off);
                ldsm4(alo[mi], stg + SA_LO + off);
            }
            #pragma unroll
            for (int h = 0; h < 2; h++) {
                uint32_t bhi[2][4], blo[2][4];
                #pragma unroll
                for (int p = 0; p < 2; p++) {
                    int row = brow0 + h*32 + p*16;
                    int chunk = ks*2 + bcbit;
                    uint32_t off = (uint32_t)(row*128 + ((chunk ^ (row & 7)) << 4));
                    ldsm4(bhi[p], stg + SB_HI + off);
                    ldsm4(blo[p], stg + SB_LO + off);
                }
                #pragma unroll
                for (int mi = 0; mi < 2; mi++)
                    #pragma unroll
                    for (int p = 0; p < 2; p++)
                        #pragma unroll
                        for (int q = 0; q < 2; q++) {
                            float* a = acc[mi][h*4 + p*2 + q];
                            mma_bf16(a, ahi[mi], &bhi[p][2*q]);
                            mma_bf16(a, alo[mi], &bhi[p][2*q]);
                            mma_bf16(a, ahi[mi], &blo[p][2*q]);
                        }
            }
        }
    }

    // epilogue
    const int gid = lane >> 2, tig = lane & 3;
    #pragma unroll
    for (int mi = 0; mi < 2; mi++) {
        #pragma unroll
        for (int j = 0; j < 8; j++) {
            int m = m0 + wm*32 + mi*16 + gid;
            int n = n0 + wn*64 + j*8 + tig*2;
            if (n < N) {
                float2 v0 = make_float2(acc[mi][j][0], acc[mi][j][1]);
                float2 v1 = make_float2(acc[mi][j][2], acc[mi][j][3]);
                if (ep == 2) {
                    const float2 r0 = *(const float2*)(resid + (size_t)m*N + n);
                    const float2 r1 = *(const float2*)(resid + (size_t)(m+8)*N + n);
                    v0.x += r0.x; v0.y += r0.y;
                    v1.x += r1.x; v1.y += r1.y;
                }
                *(float2*)(C + (size_t)m*N + n) = v0;
                *(float2*)(C + (size_t)(m+8)*N + n) = v1;
            }
        }
    }
}

// ================= other kernels =================
__global__ void embed_kernel(const int* __restrict__ ids,
                             const float* __restrict__ emb,
                             float* __restrict__ x)
{
    int idx = blockIdx.x*blockDim.x + threadIdx.x;
    if (idx >= ROWS*DM) return;
    int row = idx / DM, c = idx % DM;
    x[idx] = emb[(size_t)ids[row]*DM + c];
}

// rmsnorm + emit bf16 hi/lo split directly
__global__ void rmsnorm_split_kernel(const float* __restrict__ x,
                                     const float* __restrict__ w,
                                     __nv_bfloat16* __restrict__ ohi,
                                     __nv_bfloat16* __restrict__ olo)
{
    __shared__ float red[8];
    int row = blockIdx.x;
    const float* xr = x + (size_t)row*DM;
    float s = 0.f;
    for (int c = threadIdx.x; c < DM; c += 256) { float v = xr[c]; s += v*v; }
    #pragma unroll
    for (int o = 16; o; o >>= 1) s += __shfl_xor_sync(0xffffffffu, s, o);
    if ((threadIdx.x & 31) == 0) red[threadIdx.x >> 5] = s;
    __syncthreads();
    if (threadIdx.x < 8) {
        s = red[threadIdx.x];
        #pragma unroll
        for (int o = 4; o; o >>= 1) s += __shfl_xor_sync(0xffu, s, o);
        if (threadIdx.x == 0) red[0] = s;
    }
    __syncthreads();
    float scale = rsqrtf(red[0] / (float)DM + 1e-5f);
    for (int c = threadIdx.x; c < DM; c += 256) {
        float v = xr[c] * scale * w[c];
        __nv_bfloat16 h, l;
        bf16_split(v, h, l);
        ohi[(size_t)row*DM + c] = h;
        olo[(size_t)row*DM + c] = l;
    }
}

// small FFMA GEMM (dt_proj).  ep: 0=none, 1=softplus(acc+bias[n])
__global__ void __launch_bounds__(256, 2) gemm_nt(
    const float* __restrict__ A, int lda,
    const float* __restrict__ W,
    float* __restrict__ C,
    int N, int K, int ep,
    const float* __restrict__ bias)
{
    __shared__ float As[8][128];
    __shared__ float Bs[8][128];
    const int tid = threadIdx.x;
    const int tx = tid & 15;
    const int ty = tid >> 4;
    const int m0 = blockIdx.y * 128;
    const int n0 = blockIdx.x * 128;
    const int lr = tid >> 1;
    const int lc = (tid & 1) * 4;

    float acc[8][8];
    #pragma unroll
    for (int i = 0; i < 8; i++)
        #pragma unroll
        for (int j = 0; j < 8; j++) acc[i][j] = 0.f;

    const float* Aptr = A + (size_t)(m0 + lr)*lda + lc;
    const bool wvalid = (n0 + lr) < N;
    const float* Wptr = W + (size_t)(wvalid ? (n0 + lr) : 0)*K + lc;

    for (int k0 = 0; k0 < K; k0 += 8) {
        float4 av = *(const float4*)(Aptr + k0);
        float4 bv = make_float4(0.f, 0.f, 0.f, 0.f);
        if (wvalid) bv = *(const float4*)(Wptr + k0);
        __syncthreads();
        As[lc+0][lr] = av.x; As[lc+1][lr] = av.y; As[lc+2][lr] = av.z; As[lc+3][lr] = av.w;
        Bs[lc+0][lr] = bv.x; Bs[lc+1][lr] = bv.y; Bs[lc+2][lr] = bv.z; Bs[lc+3][lr] = bv.w;
        __syncthreads();
        #pragma unroll
        for (int k = 0; k < 8; k++) {
            float4 a0 = *(const float4*)&As[k][ty*8];
            float4 a1 = *(const float4*)&As[k][ty*8+4];
            float4 b0 = *(const float4*)&Bs[k][tx*8];
            float4 b1 = *(const float4*)&Bs[k][tx*8+4];
            float ar[8] = {a0.x,a0.y,a0.z,a0.w,a1.x,a1.y,a1.z,a1.w};
            float br[8] = {b0.x,b0.y,b0.z,b0.w,b1.x,b1.y,b1.z,b1.w};
            #pragma unroll
            for (int i = 0; i < 8; i++)
                #pragma unroll
                for (int j = 0; j < 8; j++)
                    acc[i][j] = fmaf(ar[i], br[j], acc[i][j]);
        }
    }

    #pragma unroll
    for (int i = 0; i < 8; i++) {
        int m = m0 + ty*8 + i;
        #pragma unroll
        for (int j = 0; j < 8; j++) {
            int n = n0 + tx*8 + j;
            if (n < N) {
                float v = acc[i][j];
                if (ep == 1) {
                    v += bias[n];
                    v = (v > 20.f) ? v : log1pf(expf(v));
                }
                C[(size_t)m*N + n] = v;
            }
        }
    }
}

// depthwise causal conv + bias + silu -> u (fp32) AND u hi/lo (bf16 split)
__global__ void conv_silu_kernel(const float* __restrict__ xr,
                                 const float* __restrict__ cw,
                                 const float* __restrict__ cb,
                                 float* __restrict__ u,
                                 __nv_bfloat16* __restrict__ uhi,
                                 __nv_bfloat16* __restrict__ ulo)
{
    int idx = blockIdx.x*blockDim.x + threadIdx.x;
    if (idx >= ROWS*DI) return;
    int d = idx % DI;
    int row = idx / DI;
    int t = row % L_;
    float acc = cb[d];
    #pragma unroll
    for (int j = 0; j < 4; ++j) {
        int tt = t - 3 + j;
        if (tt >= 0)
            acc = fmaf(cw[d*4 + j], xr[(size_t)(row - 3 + j)*(2*DI) + d], acc);
    }
    float v = acc / (1.f + __expf(-acc));
    u[idx] = v;
    __nv_bfloat16 h, l;
    bf16_split(v, h, l);
    uhi[idx] = h;
    ulo[idx] = l;
}

// selective scan + fused gate + bf16 split output
__global__ void scan_kernel(const float* __restrict__ delta,
                            const float* __restrict__ u,
                            const float* __restrict__ xdbl,
                            const float* __restrict__ alog,
                            const float* __restrict__ Dv,
                            const float* __restrict__ xr,
                            __nv_bfloat16* __restrict__ yhi,
                            __nv_bfloat16* __restrict__ ylo)
{
    int gid = blockIdx.x*blockDim.x + threadIdx.x;
    int ch = gid >> 4;
    if (ch >= B_*DI) return;
    int n = gid & 15;
    int b = ch / DI, d = ch % DI;
    float An = -__expf(alog[d*DS + n]);
    float Dd = Dv[d];
    float state = 0.f;
    const float* drow = delta + (size_t)b*L_*DI + d;
    const float* urow = u     + (size_t)b*L_*DI + d;
    const float* xrow = xdbl  + (size_t)b*L_*80 + DTR + n;
    const float* rrow = xr    + (size_t)b*L_*(2*DI) + DI + d;
    __nv_bfloat16* yh = yhi + (size_t)b*L_*DI + d;
    __nv_bfloat16* yl = ylo + (size_t)b*L_*DI + d;
    for (int t = 0; t < L_; ++t) {
        float dt = drow[(size_t)t*DI];
        float uu = urow[(size_t)t*DI];
        float Bn = xrow[(size_t)t*80];
        float Cn = xrow[(size_t)t*80 + DS];
        float dA = __expf(dt * An);
        state = fmaf(dA, state, dt * Bn * uu);
        float p = state * Cn;
        p += __shfl_xor_sync(0xffffffffu, p, 8);
        p += __shfl_xor_sync(0xffffffffu, p, 4);
        p += __shfl_xor_sync(0xffffffffu, p, 2);
        p += __shfl_xor_sync(0xffffffffu, p, 1);
        if (n == 0) {
            float r = rrow[(size_t)t*(2*DI)];
            float g = r / (1.f + __expf(-r));
            float yv = (p + uu * Dd) * g;
            __nv_bfloat16 h, l;
            bf16_split(yv, h, l);
            yh[(size_t)t*DI] = h;
            yl[(size_t)t*DI] = l;
        }
    }
}

// ================= launcher =================
static inline void do_split(const float* src, __nv_bfloat16* hi, __nv_bfloat16* lo, size_t n)
{
    int n4 = (int)(n >> 2);
    split_kernel<<<(n4 + 255)/256, 256>>>(src, hi, lo, n4);
}

extern "C" void kernel_launch(void* const* d_in, const int* in_sizes, int n_in,
                              void* d_out, int out_size)
{
    (void)in_sizes; (void)n_in; (void)out_size;
    const int*   ids  = (const int*)d_in[0];
    const float* emb  = (const float*)d_in[2];
    const float* inw  = (const float*)d_in[3];
    const float* cw   = (const float*)d_in[4];
    const float* cb   = (const float*)d_in[5];
    const float* xpw  = (const float*)d_in[6];
    const float* dtw  = (const float*)d_in[7];
    const float* dtb  = (const float*)d_in[8];
    const float* alog = (const float*)d_in[9];
    const float* Dv   = (const float*)d_in[10];
    const float* outw = (const float*)d_in[11];
    const float* nw   = (const float*)d_in[12];
    const float* nfw  = (const float*)d_in[13];
    float* out = (float*)d_out;

    float *x, *xr, *u, *xdbl, *delta;
    __nv_bfloat16 *ahi, *alo, *whi, *wlo;
    cudaGetSymbolAddress((void**)&x,     g_x);
    cudaGetSymbolAddress((void**)&xr,    g_xr);
    cudaGetSymbolAddress((void**)&u,     g_u);
    cudaGetSymbolAddress((void**)&xdbl,  g_xdbl);
    cudaGetSymbolAddress((void**)&delta, g_delta);
    cudaGetSymbolAddress((void**)&ahi,   g_ahi);
    cudaGetSymbolAddress((void**)&alo,   g_alo);
    cudaGetSymbolAddress((void**)&whi,   g_whi);
    cudaGetSymbolAddress((void**)&wlo,   g_wlo);

    // set every call (cheap, deterministic, capture-safe)
    cudaFuncSetAttribute(gemm_bf16, cudaFuncAttributeMaxDynamicSharedMemorySize, SM_BYTES);

    embed_kernel<<<(ROWS*DM + 255)/256, 256>>>(ids, emb, x);

    for (int l = 0; l < 2; ++l) {
        // rmsnorm -> xn split (direct)
        rmsnorm_split_kernel<<<ROWS, 256>>>(x, nw + l*DM, ahi, alo);
        // in_proj: [2048,768] @ [3072,768]^T -> xr [2048,3072]
        do_split(inw + (size_t)l*2*DI*DM, whi, wlo, (size_t)2*DI*DM);
        gemm_bf16<<<dim3(ROWS/128, (2*DI + 127)/128), 256, SM_BYTES>>>(
            ahi, alo, DM, whi, wlo, 2*DI, xr, 0, nullptr);
        // conv + silu -> u fp32 + u split (overwrites ahi/alo)
        conv_silu_kernel<<<(ROWS*DI + 255)/256, 256>>>(
            xr, cw + l*DI*4, cb + l*DI, u, ahi, alo);
        // x_dbl = u @ x_proj^T : [2048, 80]
        do_split(xpw + (size_t)l*80*DI, whi, wlo, (size_t)80*DI);
        gemm_bf16<<<dim3(ROWS/128, 1), 256, SM_BYTES>>>(
            ahi, alo, DI, whi, wlo, 80, xdbl, 0, nullptr);
        // delta = softplus(x_dbl[:, :48] @ dt_proj^T + dt_b)
        gemm_nt<<<dim3(DI/128, ROWS/128), 256>>>(
            xdbl, 80, dtw + (size_t)l*DI*DTR, delta, DI, DTR, 1, dtb + l*DI);
        // scan + gate -> y split (overwrites ahi/alo; u fp32 still intact)
        scan_kernel<<<(B_*DI*16)/256, 256>>>(
            delta, u, xdbl, alog + l*DI*DS, Dv + l*DI, xr, ahi, alo);
        // out_proj: [2048,1536] @ [768,1536]^T + x -> x
        do_split(outw + (size_t)l*DM*DI, whi, wlo, (size_t)DM*DI);
        gemm_bf16<<<dim3(ROWS/128, (DM + 127)/128), 256, SM_BYTES>>>(
            ahi, alo, DI, whi, wlo, DM, x, 2, x);
    }

    // final rmsnorm -> xn split
    rmsnorm_split_kernel<<<ROWS, 256>>>(x, nfw, ahi, alo);
    // logits: [2048,768] @ [50264,768]^T -> out [2048,50264]
    do_split(emb, whi, wlo, (size_t)VOCAB_*DM);
    gemm_bf16<<<dim3(ROWS/128, (VOCAB_ + 127)/128), 256, SM_BYTES>>>(
        ahi, alo, DM, whi, wlo, VOCAB_, out, 0, nullptr);
}

// round 15
// speedup vs baseline: 1.3615x; 1.0083x over previous
#include <cuda_runtime.h>
#include <cuda_bf16.h>
#include <math.h>
#include <stdint.h>

#define B_      2
#define L_      1024
#define DM      768
#define DI      1536
#define DS      16
#define DTR     48
#define VOCAB_  50264
#define ROWS    (B_*L_)   // 2048

// ---------------- scratch (static device memory; no allocation) ----------------
__device__ float g_x[ROWS*DM];
__device__ float g_xr[ROWS*2*DI];
__device__ float g_u[ROWS*DI];
__device__ float g_xdbl[ROWS*80];
__device__ float g_delta[ROWS*DI];
// split activation buffers (max 2048x1536)
__device__ __nv_bfloat16 g_ahi[ROWS*DI];
__device__ __nv_bfloat16 g_alo[ROWS*DI];
// split weight buffers (max = embedding 50264x768)
__device__ __nv_bfloat16 g_whi[(size_t)VOCAB_*DM];
__device__ __nv_bfloat16 g_wlo[(size_t)VOCAB_*DM];

// ================= helpers =================
__device__ __forceinline__ uint32_t smem_u32(const void* p) {
    uint32_t a;
    asm("{ .reg .u64 t; cvta.to.shared.u64 t, %1; cvt.u32.u64 %0, t; }" : "=r"(a) : "l"(p));
    return a;
}
__device__ __forceinline__ void ldsm4(uint32_t* r, uint32_t addr) {
    asm volatile("ldmatrix.sync.aligned.m8n8.x4.shared.b16 {%0,%1,%2,%3}, [%4];"
        : "=r"(r[0]), "=r"(r[1]), "=r"(r[2]), "=r"(r[3]) : "r"(addr));
}
__device__ __forceinline__ void mma_bf16(float* c, const uint32_t* a, const uint32_t* b) {
    asm volatile("mma.sync.aligned.m16n8k16.row.col.f32.bf16.bf16.f32 "
        "{%0,%1,%2,%3},{%4,%5,%6,%7},{%8,%9},{%0,%1,%2,%3};"
        : "+f"(c[0]), "+f"(c[1]), "+f"(c[2]), "+f"(c[3])
        : "r"(a[0]), "r"(a[1]), "r"(a[2]), "r"(a[3]), "r"(b[0]), "r"(b[1]));
}
__device__ __forceinline__ void cp16(uint32_t dst, const void* src, bool valid) {
    int sz = valid ? 16 : 0;
    asm volatile("cp.async.cg.shared.global [%0], [%1], 16, %2;"
                 :: "r"(dst), "l"(src), "r"(sz) : "memory");
}
__device__ __forceinline__ void cp_commit() {
    asm volatile("cp.async.commit_group;" ::: "memory");
}
__device__ __forceinline__ void bf16_split(float v, __nv_bfloat16& h, __nv_bfloat16& l) {
    h = __float2bfloat16(v);
    l = __float2bfloat16(v - __bfloat162float(h));
}

// ================= split fp32 -> bf16 hi + bf16 lo (weights) =================
__global__ void split_kernel(const float* __restrict__ in,
                             __nv_bfloat16* __restrict__ hi,
                             __nv_bfloat16* __restrict__ lo,
                             int n4)
{
    int i = blockIdx.x*blockDim.x + threadIdx.x;
    if (i >= n4) return;
    float4 v = ((const float4*)in)[i];
    __nv_bfloat16 h0,h1,h2,h3,l0,l1,l2,l3;
    bf16_split(v.x, h0, l0); bf16_split(v.y, h1, l1);
    bf16_split(v.z, h2, l2); bf16_split(v.w, h3, l3);
    ushort4 ho, lq;
    ho.x = __bfloat16_as_ushort(h0); ho.y = __bfloat16_as_ushort(h1);
    ho.z = __bfloat16_as_ushort(h2); ho.w = __bfloat16_as_ushort(h3);
    lq.x = __bfloat16_as_ushort(l0); lq.y = __bfloat16_as_ushort(l1);
    lq.z = __bfloat16_as_ushort(l2); lq.w = __bfloat16_as_ushort(l3);
    ((ushort4*)hi)[i] = ho;
    ((ushort4*)lo)[i] = lq;
}

// ================= bf16 split-precision tensor GEMM (R6/R9 proven config) ==========
// C[M,N] = A[M,K] @ W[N,K]^T, A/W pre-split bf16 hi/lo.
// acc += hi*hi + lo*hi + hi*lo (fp32 accum in mma).
// Block tile 128x128, k-chunk 64, 8 warps (4M x 2N), warp tile 32x64.
// 2-stage cp.async double buffering.  Grid: x = M-tiles, y = N-tiles.
// ep: 0 = none, 2 = acc + resid[m*N+n]
#define SA_HI 0
#define SA_LO 16384
#define SB_HI 32768
#define SB_LO 49152
#define STG   65536
#define SM_BYTES (2*STG)   // 131072

__global__ void __launch_bounds__(256, 1) gemm_bf16(
    const __nv_bfloat16* __restrict__ Ahi, const __nv_bfloat16* __restrict__ Alo, int K,
    const __nv_bfloat16* __restrict__ Bhi, const __nv_bfloat16* __restrict__ Blo, int N,
    float* __restrict__ C, int ep, const float* __restrict__ resid)
{
    extern __shared__ char sm[];
    const uint32_t sb = smem_u32(sm);
    const int tid = threadIdx.x, wid = tid >> 5, lane = tid & 31;
    const int wm = wid & 3, wn = wid >> 2;
    const int m0 = blockIdx.x * 128;
    const int n0 = blockIdx.y * 128;

    float acc[2][8][4];
    #pragma unroll
    for (int i = 0; i < 2; i++)
        #pragma unroll
        for (int j = 0; j < 8; j++)
            #pragma unroll
            for (int v = 0; v < 4; v++) acc[i][j][v] = 0.f;

    // gmem->smem load indices (each thread: 4 rows x 16B per buffer)
    const int lrow = tid >> 3;          // 0..31 base row
    const int lchk = tid & 7;           // 16B chunk within 128B row

    // ldmatrix address components
    const int arow = wm*32 + (lane & 15);
    const int acbit = lane >> 4;
    const int brow0 = wn*64 + (lane & 7) + ((lane >> 4) << 3);
    const int bcbit = (lane >> 3) & 1;

    const int nk = K >> 6;

    auto issue = [&](int kc) {
        const int s = kc & 1;
        const int k0 = kc << 6;
        const uint32_t base = sb + s*STG;
        #pragma unroll
        for (int i = 0; i < 4; i++) {
            int r = lrow + i*32;
            size_t ga = (size_t)(m0 + r)*K + k0 + lchk*8;
            uint32_t off = (uint32_t)(r*128 + ((lchk ^ (r & 7)) << 4));
            cp16(base + SA_HI + off, Ahi + ga, true);
            cp16(base + SA_LO + off, Alo + ga, true);
            int n = n0 + r;
            bool v = n < N;
            size_t gb = (size_t)(v ? n : 0)*K + k0 + lchk*8;
            cp16(base + SB_HI + off, Bhi + gb, v);
            cp16(base + SB_LO + off, Blo + gb, v);
        }
        cp_commit();
    };

    issue(0);
    for (int kc = 0; kc < nk; kc++) {
        if (kc + 1 < nk) {
            issue(kc + 1);
            asm volatile("cp.async.wait_group 1;" ::: "memory");
        } else {
            asm volatile("cp.async.wait_group 0;" ::: "memory");
        }
        __syncthreads();

        const uint32_t stg = sb + (kc & 1)*STG;
        #pragma unroll
        for (int ks = 0; ks < 4; ks++) {
            uint32_t ahi[2][4], alo[2][4];
            #pragma unroll
            for (int mi = 0; mi < 2; mi++) {
                int row = arow + mi*16;
                int chunk = ks*2 + acbit;
                uint32_t off = (uint32_t)(row*128 + ((chunk ^ (row & 7)) << 4));
                ldsm4(ahi[mi], stg + SA_HI + off);
                ldsm4(alo[mi], stg + SA_LO + off);
            }
            #pragma unroll
            for (int h = 0; h < 2; h++) {
                uint32_t bhi[2][4], blo[2][4];
                #pragma unroll
                for (int p = 0; p < 2; p++) {
                    int row = brow0 + h*32 + p*16;
                    int chunk = ks*2 + bcbit;
                    uint32_t off = (uint32_t)(row*128 + ((chunk ^ (row & 7)) << 4));
                    ldsm4(bhi[p], stg + SB_HI + off);
                    ldsm4(blo[p], stg + SB_LO + off);
                }
                #pragma unroll
                for (int mi = 0; mi < 2; mi++)
                    #pragma unroll
                    for (int p = 0; p < 2; p++)
                        #pragma unroll
                        for (int q = 0; q < 2; q++) {
                            float* a = acc[mi][h*4 + p*2 + q];
                            mma_bf16(a, ahi[mi], &bhi[p][2*q]);
                            mma_bf16(a, alo[mi], &bhi[p][2*q]);
                            mma_bf16(a, ahi[mi], &blo[p][2*q]);
                        }
            }
        }
        __syncthreads();
    }

    // epilogue
    const int gid = lane >> 2, tig = lane & 3;
    #pragma unroll
    for (int mi = 0; mi < 2; mi++) {
        #pragma unroll
        for (int j = 0; j < 8; j++) {
            int m = m0 + wm*32 + mi*16 + gid;
            int n = n0 + wn*64 + j*8 + tig*2;
            if (n < N) {
                float2 v0 = make_float2(acc[mi][j][0], acc[mi][j][1]);
                float2 v1 = make_float2(acc[mi][j][2], acc[mi][j][3]);
                if (ep == 2) {
                    const float2 r0 = *(const float2*)(resid + (size_t)m*N + n);
                    const float2 r1 = *(const float2*)(resid + (size_t)(m+8)*N + n);
                    v0.x += r0.x; v0.y += r0.y;
                    v1.x += r1.x; v1.y += r1.y;
                }
                *(float2*)(C + (size_t)m*N + n) = v0;
                *(float2*)(C + (size_t)(m+8)*N + n) = v1;
            }
        }
    }
}

// ================= other kernels =================
__global__ void embed_kernel(const int* __restrict__ ids,
                             const float* __restrict__ emb,
                             float* __restrict__ x)
{
    int idx = blockIdx.x*blockDim.x + threadIdx.x;
    if (idx >= ROWS*DM) return;
    int row = idx / DM, c = idx % DM;
    x[idx] = emb[(size_t)ids[row]*DM + c];
}

// rmsnorm + emit bf16 hi/lo split directly
__global__ void rmsnorm_split_kernel(const float* __restrict__ x,
                                     const float* __restrict__ w,
                                     __nv_bfloat16* __restrict__ ohi,
                                     __nv_bfloat16* __restrict__ olo)
{
    __shared__ float red[8];
    int row = blockIdx.x;
    const float* xr = x + (size_t)row*DM;
    float s = 0.f;
    for (int c = threadIdx.x; c < DM; c += 256) { float v = xr[c]; s += v*v; }
    #pragma unroll
    for (int o = 16; o; o >>= 1) s += __shfl_xor_sync(0xffffffffu, s, o);
    if ((threadIdx.x & 31) == 0) red[threadIdx.x >> 5] = s;
    __syncthreads();
    if (threadIdx.x < 8) {
        s = red[threadIdx.x];
        #pragma unroll
        for (int o = 4; o; o >>= 1) s += __shfl_xor_sync(0xffu, s, o);
        if (threadIdx.x == 0) red[0] = s;
    }
    __syncthreads();
    float scale = rsqrtf(red[0] / (float)DM + 1e-5f);
    for (int c = threadIdx.x; c < DM; c += 256) {
        float v = xr[c] * scale * w[c];
        __nv_bfloat16 h, l;
        bf16_split(v, h, l);
        ohi[(size_t)row*DM + c] = h;
        olo[(size_t)row*DM + c] = l;
    }
}

// small FFMA GEMM (dt_proj).  ep: 0=none, 1=softplus(acc+bias[n])
__global__ void __launch_bounds__(256, 2) gemm_nt(
    const float* __restrict__ A, int lda,
    const float* __restrict__ W,
    float* __restrict__ C,
    int N, int K, int ep,
    const float* __restrict__ bias)
{
    __shared__ float As[8][128];
    __shared__ float Bs[8][128];
    const int tid = threadIdx.x;
    const int tx = tid & 15;
    const int ty = tid >> 4;
    const int m0 = blockIdx.y * 128;
    const int n0 = blockIdx.x * 128;
    const int lr = tid >> 1;
    const int lc = (tid & 1) * 4;

    float acc[8][8];
    #pragma unroll
    for (int i = 0; i < 8; i++)
        #pragma unroll
        for (int j = 0; j < 8; j++) acc[i][j] = 0.f;

    const float* Aptr = A + (size_t)(m0 + lr)*lda + lc;
    const bool wvalid = (n0 + lr) < N;
    const float* Wptr = W + (size_t)(wvalid ? (n0 + lr) : 0)*K + lc;

    for (int k0 = 0; k0 < K; k0 += 8) {
        float4 av = *(const float4*)(Aptr + k0);
        float4 bv = make_float4(0.f, 0.f, 0.f, 0.f);
        if (wvalid) bv = *(const float4*)(Wptr + k0);
        __syncthreads();
        As[lc+0][lr] = av.x; As[lc+1][lr] = av.y; As[lc+2][lr] = av.z; As[lc+3][lr] = av.w;
        Bs[lc+0][lr] = bv.x; Bs[lc+1][lr] = bv.y; Bs[lc+2][lr] = bv.z; Bs[lc+3][lr] = bv.w;
        __syncthreads();
        #pragma unroll
        for (int k = 0; k < 8; k++) {
            float4 a0 = *(const float4*)&As[k][ty*8];
            float4 a1 = *(const float4*)&As[k][ty*8+4];
            float4 b0 = *(const float4*)&Bs[k][tx*8];
            float4 b1 = *(const float4*)&Bs[k][tx*8+4];
            float ar[8] = {a0.x,a0.y,a0.z,a0.w,a1.x,a1.y,a1.z,a1.w};
            float br[8] = {b0.x,b0.y,b0.z,b0.w,b1.x,b1.y,b1.z,b1.w};
            #pragma unroll
            for (int i = 0; i < 8; i++)
                #pragma unroll
                for (int j = 0; j < 8; j++)
                    acc[i][j] = fmaf(ar[i], br[j], acc[i][j]);
        }
    }

    #pragma unroll
    for (int i = 0; i < 8; i++) {
        int m = m0 + ty*8 + i;
        #pragma unroll
        for (int j = 0; j < 8; j++) {
            int n = n0 + tx*8 + j;
            if (n < N) {
                float v = acc[i][j];
                if (ep == 1) {
                    v += bias[n];
                    v = (v > 20.f) ? v : log1pf(expf(v));
                }
                C[(size_t)m*N + n] = v;
            }
        }
    }
}

// depthwise causal conv + bias + silu -> u (fp32) AND u hi/lo (bf16 split)
__global__ void conv_silu_kernel(const float* __restrict__ xr,
                                 const float* __restrict__ cw,
                                 const float* __restrict__ cb,
                                 float* __restrict__ u,
                                 __nv_bfloat16* __restrict__ uhi,
                                 __nv_bfloat16* __restrict__ ulo)
{
    int idx = blockIdx.x*blockDim.x + threadIdx.x;
    if (idx >= ROWS*DI) return;
    int d = idx % DI;
    int row = idx / DI;
    int t = row % L_;
    float acc = cb[d];
    #pragma unroll
    for (int j = 0; j < 4; ++j) {
        int tt = t - 3 + j;
        if (tt >= 0)
            acc = fmaf(cw[d*4 + j], xr[(size_t)(row - 3 + j)*(2*DI) + d], acc);
    }
    float v = acc / (1.f + __expf(-acc));
    u[idx] = v;
    __nv_bfloat16 h, l;
    bf16_split(v, h, l);
    uhi[idx] = h;
    ulo[idx] = l;
}

// selective scan + fused gate + bf16 split output
__global__ void scan_kernel(const float* __restrict__ delta,
                            const float* __restrict__ u,
                            const float* __restrict__ xdbl,
                            const float* __restrict__ alog,
                            const float* __restrict__ Dv,
                            const float* __restrict__ xr,
                            __nv_bfloat16* __restrict__ yhi,
                            __nv_bfloat16* __restrict__ ylo)
{
    int gid = blockIdx.x*blockDim.x + threadIdx.x;
    int ch = gid >> 4;
    if (ch >= B_*DI) return;
    int n = gid & 15;
    int b = ch / DI, d = ch % DI;
    float An = -__expf(alog[d*DS + n]);
    float Dd = Dv[d];
    float state = 0.f;
    const float* drow = delta + (size_t)b*L_*DI + d;
    const float* urow = u     + (size_t)b*L_*DI + d;
    const float* xrow = xdbl  + (size_t)b*L_*80 + DTR + n;
    const float* rrow = xr    + (size_t)b*L_*(2*DI) + DI + d;
    __nv_bfloat16* yh = yhi + (size_t)b*L_*DI + d;
    __nv_bfloat16* yl = ylo + (size_t)b*L_*DI + d;
    for (int t = 0; t < L_; ++t) {
        float dt = drow[(size_t)t*DI];
        float uu = urow[(size_t)t*DI];
        float Bn = xrow[(size_t)t*80];
        float Cn = xrow[(size_t)t*80 + DS];
        float dA = __expf(dt * An);
        state = fmaf(dA, state, dt * Bn * uu);
        float p = state * Cn;
        p += __shfl_xor_sync(0xffffffffu, p, 8);
        p += __shfl_xor_sync(0xffffffffu, p, 4);
        p += __shfl_xor_sync(0xffffffffu, p, 2);
        p += __shfl_xor_sync(0xffffffffu, p, 1);
        if (n == 0) {
            float r = rrow[(size_t)t*(2*DI)];
            float g = r / (1.f + __expf(-r));
            float yv = (p + uu * Dd) * g;
            __nv_bfloat16 h, l;
            bf16_split(yv, h, l);
            yh[(size_t)t*DI] = h;
            yl[(size_t)t*DI] = l;
        }
    }
}

// ================= launcher =================
static inline void do_split(const float* src, __nv_bfloat16* hi, __nv_bfloat16* lo, size_t n)
{
    int n4 = (int)(n >> 2);
    split_kernel<<<(n4 + 255)/256, 256>>>(src, hi, lo, n4);
}

extern "C" void kernel_launch(void* const* d_in, const int* in_sizes, int n_in,
                              void* d_out, int out_size)
{
    (void)in_sizes; (void)n_in; (void)out_size;
    const int*   ids  = (const int*)d_in[0];
    const float* emb  = (const float*)d_in[2];
    const float* inw  = (const float*)d_in[3];
    const float* cw   = (const float*)d_in[4];
    const float* cb   = (const float*)d_in[5];
    const float* xpw  = (const float*)d_in[6];
    const float* dtw  = (const float*)d_in[7];
    const float* dtb  = (const float*)d_in[8];
    const float* alog = (const float*)d_in[9];
    const float* Dv   = (const float*)d_in[10];
    const float* outw = (const float*)d_in[11];
    const float* nw   = (const float*)d_in[12];
    const float* nfw  = (const float*)d_in[13];
    float* out = (float*)d_out;

    float *x, *xr, *u, *xdbl, *delta;
    __nv_bfloat16 *ahi, *alo, *whi, *wlo;
    cudaGetSymbolAddress((void**)&x,     g_x);
    cudaGetSymbolAddress((void**)&xr,    g_xr);
    cudaGetSymbolAddress((void**)&u,     g_u);
    cudaGetSymbolAddress((void**)&xdbl,  g_xdbl);
    cudaGetSymbolAddress((void**)&delta, g_delta);
    cudaGetSymbolAddress((void**)&ahi,   g_ahi);
    cudaGetSymbolAddress((void**)&alo,   g_alo);
    cudaGetSymbolAddress((void**)&whi,   g_whi);
    cudaGetSymbolAddress((void**)&wlo,   g_wlo);

    // set every call (cheap, deterministic, capture-safe)
    cudaFuncSetAttribute(gemm_bf16, cudaFuncAttributeMaxDynamicSharedMemorySize, SM_BYTES);

    embed_kernel<<<(ROWS*DM + 255)/256, 256>>>(ids, emb, x);

    for (int l = 0; l < 2; ++l) {
        // rmsnorm -> xn split (direct)
        rmsnorm_split_kernel<<<ROWS, 256>>>(x, nw + l*DM, ahi, alo);
        // in_proj: [2048,768] @ [3072,768]^T -> xr [2048,3072]
        do_split(inw + (size_t)l*2*DI*DM, whi, wlo, (size_t)2*DI*DM);
        gemm_bf16<<<dim3(ROWS/128, (2*DI + 127)/128), 256, SM_BYTES>>>(
            ahi, alo, DM, whi, wlo, 2*DI, xr, 0, nullptr);
        // conv + silu -> u fp32 + u split (overwrites ahi/alo)
        conv_silu_kernel<<<(ROWS*DI + 255)/256, 256>>>(
            xr, cw + l*DI*4, cb + l*DI, u, ahi, alo);
        // x_dbl = u @ x_proj^T : [2048, 80]
        do_split(xpw + (size_t)l*80*DI, whi, wlo, (size_t)80*DI);
        gemm_bf16<<<dim3(ROWS/128, 1), 256, SM_BYTES>>>(
            ahi, alo, DI, whi, wlo, 80, xdbl, 0, nullptr);
        // delta = softplus(x_dbl[:, :48] @ dt_proj^T + dt_b)
        gemm_nt<<<dim3(DI/128, ROWS/128), 256>>>(
            xdbl, 80, dtw + (size_t)l*DI*DTR, delta, DI, DTR, 1, dtb + l*DI);
        // scan + gate -> y split (overwrites ahi/alo; u fp32 still intact)
        scan_kernel<<<(B_*DI*16)/256, 256>>>(
            delta, u, xdbl, alog + l*DI*DS, Dv + l*DI, xr, ahi, alo);
        // out_proj: [2048,1536] @ [768,1536]^T + x -> x
        do_split(outw + (size_t)l*DM*DI, whi, wlo, (size_t)DM*DI);
        gemm_bf16<<<dim3(ROWS/128, (DM + 127)/128), 256, SM_BYTES>>>(
            ahi, alo, DI, whi, wlo, DM, x, 2, x);
    }

    // final rmsnorm -> xn split
    rmsnorm_split_kernel<<<ROWS, 256>>>(x, nfw, ahi, alo);
    // logits: [2048,768] @ [50264,768]^T -> out [2048,50264]
    do_split(emb, whi, wlo, (size_t)VOCAB_*DM);
    gemm_bf16<<<dim3(ROWS/128, (VOCAB_ + 127)/128), 256, SM_BYTES>>>(
        ahi, alo, DM, whi, wlo, VOCAB_, out, 0, nullptr);
}